// round 1
// baseline (speedup 1.0000x reference)
#include <cuda_runtime.h>
#include <math.h>

#define Bb 8
#define Nn 1024
#define Dd 512
#define Hh 8
#define DhD 64
#define Ff 2048
#define Ee 8
#define DEPTH 2
#define T (Bb*Nn)          // 8192 tokens
#define CAP T              // worst-case tokens per expert
#define QKVC (3*Dd)        // 1536

// ---------------- scratch (static device globals; no allocation) ----------------
__device__ float g_x[T*Dd];
__device__ float g_xn[T*Dd];
__device__ float g_qkv[T*QKVC];
__device__ float g_o[T*Dd];
__device__ float g_h[(size_t)Ee*CAP*Ff];     // expert hidden activations (512MB, worst case)
__device__ int   g_cnt[Ee];
__device__ int   g_tok[Ee*CAP];
__device__ float g_wgt[Ee*CAP];

// ---------------- LayerNorm (optionally affine) ----------------
__global__ void ln_kernel(const float* __restrict__ x, float* __restrict__ out,
                          const float* __restrict__ s, const float* __restrict__ b,
                          int affine) {
    int t = blockIdx.x;
    int tid = threadIdx.x;                       // 256 threads, 2 elems each
    const float* xr = x + (size_t)t*Dd;
    float v0 = xr[tid], v1 = xr[tid+256];
    float sum = v0+v1, sq = v0*v0+v1*v1;
    #pragma unroll
    for (int o=16;o>0;o>>=1){
        sum += __shfl_xor_sync(0xffffffffu,sum,o);
        sq  += __shfl_xor_sync(0xffffffffu,sq ,o);
    }
    __shared__ float ssum[8], ssq[8];
    int w = tid>>5, l = tid&31;
    if (l==0){ ssum[w]=sum; ssq[w]=sq; }
    __syncthreads();
    float ts=0.f, tq=0.f;
    #pragma unroll
    for (int i=0;i<8;i++){ ts+=ssum[i]; tq+=ssq[i]; }
    float mu = ts*(1.f/Dd);
    float var = tq*(1.f/Dd) - mu*mu;
    float rs = rsqrtf(var + 1e-5f);
    float* orow = out + (size_t)t*Dd;
    if (affine){
        orow[tid]     = (v0-mu)*rs*s[tid]     + b[tid];
        orow[tid+256] = (v1-mu)*rs*s[tid+256] + b[tid+256];
    } else {
        orow[tid]     = (v0-mu)*rs;
        orow[tid+256] = (v1-mu)*rs;
    }
}

// ---------------- generic SGEMM: C = A@B (+bias) (+residual in C) ----------------
// BM=BN=64, BK=16, 256 threads, 4x4 per thread
#define FMA16() do { \
    c[0][0]+=a.x*bv.x; c[0][1]+=a.x*bv.y; c[0][2]+=a.x*bv.z; c[0][3]+=a.x*bv.w; \
    c[1][0]+=a.y*bv.x; c[1][1]+=a.y*bv.y; c[1][2]+=a.y*bv.z; c[1][3]+=a.y*bv.w; \
    c[2][0]+=a.z*bv.x; c[2][1]+=a.z*bv.y; c[2][2]+=a.z*bv.z; c[2][3]+=a.z*bv.w; \
    c[3][0]+=a.w*bv.x; c[3][1]+=a.w*bv.y; c[3][2]+=a.w*bv.z; c[3][3]+=a.w*bv.w; } while(0)

template<int RESID>
__global__ __launch_bounds__(256)
void sgemm_kernel(const float* __restrict__ A, const float* __restrict__ Bw,
                  const float* __restrict__ bias, float* __restrict__ C,
                  int M, int Ncols, int K) {
    __shared__ float As[16][68];
    __shared__ float Bs[16][68];
    int bm = blockIdx.y*64, bn = blockIdx.x*64;
    int tid = threadIdx.x;
    int tx = tid & 15, ty = tid >> 4;
    int ar = tid>>2, ak = (tid&3)*4;
    int br = tid>>4, bc = (tid&15)*4;
    float c[4][4] = {};
    const float* Aptr = A  + (size_t)(bm+ar)*K + ak;
    const float* Bptr = Bw + (size_t)br*Ncols + bn + bc;
    for (int k0=0;k0<K;k0+=16){
        float4 av = *(const float4*)(Aptr + k0);
        As[ak+0][ar]=av.x; As[ak+1][ar]=av.y; As[ak+2][ar]=av.z; As[ak+3][ar]=av.w;
        *(float4*)&Bs[br][bc] = *(const float4*)(Bptr + (size_t)k0*Ncols);
        __syncthreads();
        #pragma unroll
        for (int k=0;k<16;k++){
            float4 a  = *(const float4*)&As[k][ty*4];
            float4 bv = *(const float4*)&Bs[k][tx*4];
            FMA16();
        }
        __syncthreads();
    }
    #pragma unroll
    for (int i=0;i<4;i++){
        int m = bm + ty*4 + i;
        #pragma unroll
        for (int j=0;j<4;j++){
            int n = bn + tx*4 + j;
            float v = c[i][j];
            if (bias) v += bias[n];
            if (RESID) v += C[(size_t)m*Ncols + n];
            C[(size_t)m*Ncols + n] = v;
        }
    }
}

// ---------------- flash attention: per (b,h) x 64-query blocks, 64 threads ----------------
__global__ __launch_bounds__(64)
void attn_kernel(const float* __restrict__ qkv, float* __restrict__ o) {
    int bh = blockIdx.x;
    int b = bh/Hh, h = bh%Hh;
    int q0 = blockIdx.y*64;
    int t = threadIdx.x;
    const float* base = qkv + (size_t)b*Nn*QKVC;
    float q[64];
    {
        const float* qp = base + (size_t)(q0+t)*QKVC + h*64;
        #pragma unroll
        for (int d=0; d<64; d+=4){
            float4 v = *(const float4*)&qp[d];
            q[d]=v.x*0.125f; q[d+1]=v.y*0.125f; q[d+2]=v.z*0.125f; q[d+3]=v.w*0.125f;
        }
    }
    float m = -INFINITY, lsum = 0.f;
    float acc[64];
    #pragma unroll
    for (int d=0;d<64;d++) acc[d]=0.f;
    __shared__ float ks[32][64];
    __shared__ float vs[32][64];
    for (int j0=0;j0<Nn;j0+=32){
        __syncthreads();
        for (int idx = t; idx < 32*16; idx += 64) {   // 512 float4 per tile
            int row = idx>>4, c4 = (idx&15)*4;
            const float* kvb = base + (size_t)(j0+row)*QKVC + h*64;
            *(float4*)&ks[row][c4] = *(const float4*)&kvb[512  + c4];
            *(float4*)&vs[row][c4] = *(const float4*)&kvb[1024 + c4];
        }
        __syncthreads();
        float s[32];
        float tmax = -INFINITY;
        #pragma unroll 4
        for (int j=0;j<32;j++){
            float a0=0.f;
            #pragma unroll
            for (int d4=0; d4<64; d4+=4){
                float4 kv = *(const float4*)&ks[j][d4];
                a0 += q[d4]*kv.x + q[d4+1]*kv.y + q[d4+2]*kv.z + q[d4+3]*kv.w;
            }
            s[j]=a0; tmax = fmaxf(tmax, a0);
        }
        float mnew = fmaxf(m, tmax);
        float alpha = __expf(m - mnew);    // first tile: exp(-inf)=0
        m = mnew;
        lsum *= alpha;
        #pragma unroll
        for (int d=0;d<64;d++) acc[d]*=alpha;
        #pragma unroll 2
        for (int j=0;j<32;j++){
            float p = __expf(s[j]-m);
            lsum += p;
            #pragma unroll
            for (int d4=0; d4<64; d4+=4){
                float4 vv = *(const float4*)&vs[j][d4];
                acc[d4]+=p*vv.x; acc[d4+1]+=p*vv.y; acc[d4+2]+=p*vv.z; acc[d4+3]+=p*vv.w;
            }
        }
    }
    float inv = 1.f/lsum;
    float* op = o + (size_t)(b*Nn + q0+t)*Dd + h*64;
    #pragma unroll
    for (int d=0; d<64; d+=4){
        float4 v; v.x=acc[d]*inv; v.y=acc[d+1]*inv; v.z=acc[d+2]*inv; v.w=acc[d+3]*inv;
        *(float4*)&op[d] = v;
    }
}

// ---------------- router: warp per token; top-2 masked softmax; expert bucketing ----------------
__global__ void reset_cnt_kernel(){ if (threadIdx.x < Ee) g_cnt[threadIdx.x]=0; }

__global__ void router_kernel(int layer, const float* __restrict__ rtw,
                              const float* __restrict__ rtb, float* __restrict__ wout) {
    int gw = (blockIdx.x*blockDim.x + threadIdx.x) >> 5;
    int lane = threadIdx.x & 31;
    if (gw >= T) return;
    const float* xr = g_x + (size_t)gw*Dd;
    const float* w = rtw + (size_t)layer*Dd*Ee;
    float acc[8] = {};
    for (int d=lane; d<Dd; d+=32){
        float xv = xr[d];
        const float* wr = w + d*Ee;
        #pragma unroll
        for (int e=0;e<8;e++) acc[e] += xv*wr[e];
    }
    #pragma unroll
    for (int e=0;e<8;e++){
        #pragma unroll
        for (int o=16;o>0;o>>=1) acc[e] += __shfl_xor_sync(0xffffffffu, acc[e], o);
    }
    if (lane==0){
        const float* bb = rtb + layer*Ee;
        float lg[8];
        #pragma unroll
        for (int e=0;e<8;e++) lg[e] = acc[e] + bb[e];
        float m1=-INFINITY, m2=-INFINITY;
        #pragma unroll
        for (int e=0;e<8;e++){
            float v=lg[e];
            if (v>m1){ m2=m1; m1=v; } else if (v>m2){ m2=v; }
        }
        float ssum=0.f, wv[8];
        #pragma unroll
        for (int e=0;e<8;e++){
            if (lg[e] >= m2){ wv[e]=expf(lg[e]-m1); ssum+=wv[e]; } else wv[e]=0.f;
        }
        float inv = 1.f/ssum;
        float* wo = wout + ((size_t)layer*T + gw)*Ee;
        #pragma unroll
        for (int e=0;e<8;e++){
            float we = wv[e]*inv;
            wo[e] = we;
            if (wv[e] > 0.f){
                int p = atomicAdd(&g_cnt[e], 1);
                g_tok[e*CAP+p] = gw;
                g_wgt[e*CAP+p] = we;
            }
        }
    }
}

// ---------------- MoE expert FC1: gather + LN2-affine fused + GELU ----------------
__global__ __launch_bounds__(256)
void moe_w1_kernel(int layer, const float* __restrict__ w1, const float* __restrict__ b1,
                   const float* __restrict__ ln2s, const float* __restrict__ ln2b) {
    int e = blockIdx.z;
    int count = g_cnt[e];
    int m0 = blockIdx.y*64;
    if (m0 >= count) return;
    int n0 = blockIdx.x*64;
    __shared__ float As[16][68];
    __shared__ float Bs[16][68];
    __shared__ int toks[64];
    int tid = threadIdx.x;
    if (tid < 64) toks[tid] = g_tok[e*CAP + min(m0+tid, count-1)];
    __syncthreads();
    const float* w1e = w1   + ((size_t)layer*Ee + e)*Dd*Ff;
    const float* se  = ln2s + ((size_t)layer*Ee + e)*Dd;
    const float* be  = ln2b + ((size_t)layer*Ee + e)*Dd;
    const float* b1e = b1   + ((size_t)layer*Ee + e)*Ff;
    int tx = tid & 15, ty = tid >> 4;
    int ar = tid>>2, ak = (tid&3)*4;
    int br = tid>>4, bc = (tid&15)*4;
    int tokr = toks[ar];
    float c[4][4] = {};
    for (int k0=0;k0<Dd;k0+=16){
        float4 xv = *(const float4*)&g_xn[(size_t)tokr*Dd + k0 + ak];
        float4 sv = *(const float4*)&se[k0+ak];
        float4 bv2 = *(const float4*)&be[k0+ak];
        As[ak+0][ar]=xv.x*sv.x+bv2.x; As[ak+1][ar]=xv.y*sv.y+bv2.y;
        As[ak+2][ar]=xv.z*sv.z+bv2.z; As[ak+3][ar]=xv.w*sv.w+bv2.w;
        *(float4*)&Bs[br][bc] = *(const float4*)&w1e[(size_t)(k0+br)*Ff + n0 + bc];
        __syncthreads();
        #pragma unroll
        for (int k=0;k<16;k++){
            float4 a  = *(const float4*)&As[k][ty*4];
            float4 bv = *(const float4*)&Bs[k][tx*4];
            FMA16();
        }
        __syncthreads();
    }
    #pragma unroll
    for (int i=0;i<4;i++){
        int mrow = m0 + ty*4 + i;
        if (mrow < count){
            #pragma unroll
            for (int j=0;j<4;j++){
                int n = n0 + tx*4 + j;
                float v = c[i][j] + b1e[n];
                float g = 0.5f*v*(1.f + erff(v*0.70710678118654752f));
                g_h[((size_t)e*CAP + mrow)*Ff + n] = g;
            }
        }
    }
}

// ---------------- MoE expert FC2: H@w2 + b2, weighted atomic accumulate into x ----------------
__global__ __launch_bounds__(256)
void moe_w2_kernel(int layer, const float* __restrict__ w2, const float* __restrict__ b2) {
    int e = blockIdx.z;
    int count = g_cnt[e];
    int m0 = blockIdx.y*64;
    if (m0 >= count) return;
    int n0 = blockIdx.x*64;
    __shared__ float As[16][68];
    __shared__ float Bs[16][68];
    __shared__ int   toks[64];
    __shared__ float wgts[64];
    int tid = threadIdx.x;
    if (tid < 64){
        int r = min(m0+tid, count-1);
        toks[tid] = g_tok[e*CAP + r];
        wgts[tid] = g_wgt[e*CAP + r];
    }
    __syncthreads();
    const float* w2e = w2 + ((size_t)layer*Ee + e)*Ff*Dd;
    const float* b2e = b2 + ((size_t)layer*Ee + e)*Dd;
    int tx = tid & 15, ty = tid >> 4;
    int ar = tid>>2, ak = (tid&3)*4;
    int br = tid>>4, bc = (tid&15)*4;
    const float* Arow = &g_h[((size_t)e*CAP + m0 + ar)*Ff + ak];
    float c[4][4] = {};
    for (int k0=0;k0<Ff;k0+=16){
        float4 av = *(const float4*)(Arow + k0);
        As[ak+0][ar]=av.x; As[ak+1][ar]=av.y; As[ak+2][ar]=av.z; As[ak+3][ar]=av.w;
        *(float4*)&Bs[br][bc] = *(const float4*)&w2e[(size_t)(k0+br)*Dd + n0 + bc];
        __syncthreads();
        #pragma unroll
        for (int k=0;k<16;k++){
            float4 a  = *(const float4*)&As[k][ty*4];
            float4 bv = *(const float4*)&Bs[k][tx*4];
            FMA16();
        }
        __syncthreads();
    }
    #pragma unroll
    for (int i=0;i<4;i++){
        int mrow = m0 + ty*4 + i;
        if (mrow < count){
            float wgt = wgts[ty*4+i];
            int tok = toks[ty*4+i];
            #pragma unroll
            for (int j=0;j<4;j++){
                int n = n0 + tx*4 + j;
                float y = c[i][j] + b2e[n];
                atomicAdd(&g_x[(size_t)tok*Dd + n], wgt*y);
            }
        }
    }
}

// ---------------- host launcher ----------------
extern "C" void kernel_launch(void* const* d_in, const int* in_sizes, int n_in,
                              void* d_out, int out_size) {
    const float* x_in  = (const float*)d_in[0];
    const float* ln1_s = (const float*)d_in[1];
    const float* ln1_b = (const float*)d_in[2];
    const float* qkv_w = (const float*)d_in[3];
    const float* out_w = (const float*)d_in[4];
    const float* out_b = (const float*)d_in[5];
    const float* rt_w  = (const float*)d_in[6];
    const float* rt_b  = (const float*)d_in[7];
    const float* ln2_s = (const float*)d_in[8];
    const float* ln2_b = (const float*)d_in[9];
    const float* w1    = (const float*)d_in[10];
    const float* b1    = (const float*)d_in[11];
    const float* w2    = (const float*)d_in[12];
    const float* b2    = (const float*)d_in[13];
    float* out = (float*)d_out;

    float *p_x, *p_xn, *p_qkv, *p_o;
    cudaGetSymbolAddress((void**)&p_x,   g_x);
    cudaGetSymbolAddress((void**)&p_xn,  g_xn);
    cudaGetSymbolAddress((void**)&p_qkv, g_qkv);
    cudaGetSymbolAddress((void**)&p_o,   g_o);

    cudaMemcpyAsync(p_x, x_in, sizeof(float)*T*Dd, cudaMemcpyDeviceToDevice);

    for (int L=0; L<DEPTH; L++){
        // LN1
        ln_kernel<<<T,256>>>(p_x, p_xn, ln1_s + (size_t)L*Dd, ln1_b + (size_t)L*Dd, 1);
        // QKV projection: [8192,512] @ [512,1536]
        sgemm_kernel<0><<<dim3(QKVC/64, T/64), 256>>>(p_xn, qkv_w + (size_t)L*Dd*QKVC,
                                                      nullptr, p_qkv, T, QKVC, Dd);
        // attention
        attn_kernel<<<dim3(Bb*Hh, Nn/64), 64>>>(p_qkv, p_o);
        // out projection + residual: x += o@W + b
        sgemm_kernel<1><<<dim3(Dd/64, T/64), 256>>>(p_o, out_w + (size_t)L*Dd*Dd,
                                                    out_b + (size_t)L*Dd, p_x, T, Dd, Dd);
        // routing
        reset_cnt_kernel<<<1,32>>>();
        router_kernel<<<T/8, 256>>>(L, rt_w, rt_b, out + (size_t)T*Dd);
        // LN2 (raw xhat; per-expert affine fused into moe_w1 A-load)
        ln_kernel<<<T,256>>>(p_x, p_xn, nullptr, nullptr, 0);
        // MoE FC1 (gather, GELU) and FC2 (weighted accumulate)
        moe_w1_kernel<<<dim3(Ff/64, CAP/64, Ee), 256>>>(L, w1, b1, ln2_s, ln2_b);
        moe_w2_kernel<<<dim3(Dd/64, CAP/64, Ee), 256>>>(L, w2, b2);
    }
    cudaMemcpyAsync(out, p_x, sizeof(float)*T*Dd, cudaMemcpyDeviceToDevice);
}

// round 12
// speedup vs baseline: 1.8111x; 1.8111x over previous
#include <cuda_runtime.h>
#include <cuda_bf16.h>
#include <math.h>
#include <stdint.h>

#define Bb 8
#define Nn 1024
#define Dd 512
#define Hh 8
#define Ff 2048
#define Ee 8
#define DEPTH 2
#define T (Bb*Nn)          // 8192 tokens
#define CAP T
#define QKVC (3*Dd)        // 1536

// ---------------- scratch (static device globals; no allocation) ----------------
__device__ float g_x[T*Dd];
__device__ float g_xn[T*Dd];                    // ln2 raw xhat (fp32)
__device__ float g_qkv[T*QKVC];
__device__ __nv_bfloat16 g_xn_hi[T*Dd], g_xn_lo[T*Dd];      // ln1 output split
__device__ __nv_bfloat16 g_o_hi[T*Dd],  g_o_lo[T*Dd];       // attention output split
__device__ __nv_bfloat16 g_a1_hi[(size_t)Ee*CAP*Dd], g_a1_lo[(size_t)Ee*CAP*Dd];
__device__ __nv_bfloat16 g_h_hi[(size_t)Ee*CAP*Ff],  g_h_lo[(size_t)Ee*CAP*Ff];
// weights transposed to [N][K] K-major, bf16 hi/lo
__device__ __nv_bfloat16 g_wq_hi[(size_t)DEPTH*QKVC*Dd], g_wq_lo[(size_t)DEPTH*QKVC*Dd];
__device__ __nv_bfloat16 g_wo_hi[(size_t)DEPTH*Dd*Dd],   g_wo_lo[(size_t)DEPTH*Dd*Dd];
__device__ __nv_bfloat16 g_w1_hi[(size_t)DEPTH*Ee*Ff*Dd], g_w1_lo[(size_t)DEPTH*Ee*Ff*Dd];
__device__ __nv_bfloat16 g_w2_hi[(size_t)DEPTH*Ee*Dd*Ff], g_w2_lo[(size_t)DEPTH*Ee*Dd*Ff];
__device__ int   g_cnt[Ee];
__device__ int   g_tok[Ee*CAP];
__device__ float g_wgt[Ee*CAP];

// ---------------- helpers (compute_103-safe: sm_80-era ISA only) ----------------
__device__ __forceinline__ uint32_t smem_u32(const void* p){
    uint32_t a;
    asm("{ .reg .u64 t; cvta.to.shared.u64 t, %1; cvt.u32.u64 %0, t; }" : "=r"(a) : "l"(p));
    return a;
}
#define LDM4(r, addr) \
    asm volatile("ldmatrix.sync.aligned.m8n8.x4.shared.b16 {%0,%1,%2,%3}, [%4];" \
        : "=r"((r)[0]), "=r"((r)[1]), "=r"((r)[2]), "=r"((r)[3]) : "r"(addr))
#define LDM2(r, addr) \
    asm volatile("ldmatrix.sync.aligned.m8n8.x2.shared.b16 {%0,%1}, [%2];" \
        : "=r"((r)[0]), "=r"((r)[1]) : "r"(addr))
#define MMA(acc, a, b) \
    asm volatile("mma.sync.aligned.m16n8k16.row.col.f32.bf16.bf16.f32 " \
        "{%0,%1,%2,%3},{%4,%5,%6,%7},{%8,%9},{%0,%1,%2,%3};" \
        : "+f"((acc)[0]), "+f"((acc)[1]), "+f"((acc)[2]), "+f"((acc)[3]) \
        : "r"((a)[0]), "r"((a)[1]), "r"((a)[2]), "r"((a)[3]), "r"((b)[0]), "r"((b)[1]))

#define PITCHB 80            // smem row pitch in bytes (32 bf16 + 8 pad) — ldmatrix conflict-free
#define TSB    (128*PITCHB)  // one tensor, one stage: 10240 B
#define STAGEB (4*TSB)       // Ah,Al,Bh,Bl: 40960 B
#define DSMEM_BYTES (2*STAGEB)

// ---------------- HMMA mainloop: acc += split(A[128xK]) @ split(B[128xK])^T ----------------
// A: [M][K] row-major bf16 (hi/lo), B: [N][K] row-major bf16 (hi/lo). 256 threads.
__device__ __forceinline__ void mma_mainloop(
    char* sm,
    const __nv_bfloat16* __restrict__ Ah, const __nv_bfloat16* __restrict__ Al,
    const __nv_bfloat16* __restrict__ Bh, const __nv_bfloat16* __restrict__ Bl,
    int K, float acc[4][4][4])
{
    const int tid  = threadIdx.x;
    const int lane = tid & 31;
    const int wid  = tid >> 5;
    const int wm   = wid >> 2;          // 0..1
    const int wn   = wid & 3;           // 0..3
    const int NC   = K >> 5;            // K/32 stages
    const int lrow = tid >> 2;          // 0..63 (and +64)
    const int lcol = (tid & 3) * 8;     // bf16 column offset (16B chunks)
    const int scol = (tid & 3) * 16;    // byte offset in smem row

    const __nv_bfloat16* srcs[4] = {Ah, Al, Bh, Bl};

    // ldmatrix per-lane offsets
    const int arow = (lane & 7) + ((lane >> 3) & 1) * 8;
    const int acol = (lane >> 4) * 8;           // bf16
    const int brow = lane & 7;
    const int bcol = ((lane >> 3) & 1) * 8;     // bf16

    // preload stage 0
    #pragma unroll
    for (int t = 0; t < 4; t++){
        uint4 a = *(const uint4*)(srcs[t] + (size_t)lrow*K + lcol);
        uint4 b = *(const uint4*)(srcs[t] + (size_t)(lrow+64)*K + lcol);
        char* d = sm + t*TSB;
        *(uint4*)(d + lrow*PITCHB + scol) = a;
        *(uint4*)(d + (lrow+64)*PITCHB + scol) = b;
    }
    __syncthreads();

    for (int kc = 0; kc < NC; kc++){
        int s = kc & 1;
        bool nxt = (kc + 1 < NC);
        uint4 v[4][2];
        if (nxt){
            int kb = (kc + 1) * 32;
            #pragma unroll
            for (int t = 0; t < 4; t++){
                v[t][0] = *(const uint4*)(srcs[t] + (size_t)lrow*K + kb + lcol);
                v[t][1] = *(const uint4*)(srcs[t] + (size_t)(lrow+64)*K + kb + lcol);
            }
        }
        uint32_t uS = smem_u32(sm + s*STAGEB);
        #pragma unroll
        for (int ks = 0; ks < 2; ks++){
            const int kk = ks * 16;
            uint32_t ah[4][4], al[4][4], bh[4][2], bl[4][2];
            #pragma unroll
            for (int mi = 0; mi < 4; mi++){
                uint32_t ro = (uint32_t)(wm*64 + mi*16 + arow)*PITCHB + (kk + acol)*2;
                LDM4(ah[mi], uS + 0*TSB + ro);
                LDM4(al[mi], uS + 1*TSB + ro);
            }
            #pragma unroll
            for (int ni = 0; ni < 4; ni++){
                uint32_t ro = (uint32_t)(wn*32 + ni*8 + brow)*PITCHB + (kk + bcol)*2;
                LDM2(bh[ni], uS + 2*TSB + ro);
                LDM2(bl[ni], uS + 3*TSB + ro);
            }
            #pragma unroll
            for (int mi = 0; mi < 4; mi++)
                #pragma unroll
                for (int ni = 0; ni < 4; ni++){
                    MMA(acc[mi][ni], ah[mi], bh[ni]);
                    MMA(acc[mi][ni], ah[mi], bl[ni]);
                    MMA(acc[mi][ni], al[mi], bh[ni]);
                }
        }
        if (nxt){
            char* d = sm + (s^1)*STAGEB;
            #pragma unroll
            for (int t = 0; t < 4; t++){
                *(uint4*)(d + t*TSB + lrow*PITCHB + scol) = v[t][0];
                *(uint4*)(d + t*TSB + (lrow+64)*PITCHB + scol) = v[t][1];
            }
            __syncthreads();
        }
    }
}

// epilogue index helper: fragment (mi,ni,reg) -> rows gm/gm+8, cols gn/gn+1
#define EPI_SETUP() \
    const int lane = threadIdx.x & 31; \
    const int wid  = threadIdx.x >> 5; \
    const int erow = (wid >> 2)*64 + (lane >> 2); \
    const int ecol = (wid & 3)*32 + (lane & 3)*2;

// ---------------- GEMM kernels ----------------
__global__ __launch_bounds__(256,1)
void mm_qkv(int L){
    int n0 = blockIdx.x*128, m0 = blockIdx.y*128;
    extern __shared__ char sm[];
    float acc[4][4][4] = {};
    mma_mainloop(sm,
        g_xn_hi + (size_t)m0*Dd, g_xn_lo + (size_t)m0*Dd,
        g_wq_hi + ((size_t)L*QKVC + n0)*Dd, g_wq_lo + ((size_t)L*QKVC + n0)*Dd,
        Dd, acc);
    EPI_SETUP();
    #pragma unroll
    for (int mi = 0; mi < 4; mi++){
        int gm = m0 + erow + mi*16;
        #pragma unroll
        for (int ni = 0; ni < 4; ni++){
            int gn = n0 + ecol + ni*8;
            *(float2*)&g_qkv[(size_t)gm*QKVC + gn]     = make_float2(acc[mi][ni][0], acc[mi][ni][1]);
            *(float2*)&g_qkv[(size_t)(gm+8)*QKVC + gn] = make_float2(acc[mi][ni][2], acc[mi][ni][3]);
        }
    }
}

__global__ __launch_bounds__(256,1)
void mm_outproj(int L, const float* __restrict__ out_b){
    int n0 = blockIdx.x*128, m0 = blockIdx.y*128;
    extern __shared__ char sm[];
    float acc[4][4][4] = {};
    mma_mainloop(sm,
        g_o_hi + (size_t)m0*Dd, g_o_lo + (size_t)m0*Dd,
        g_wo_hi + ((size_t)L*Dd + n0)*Dd, g_wo_lo + ((size_t)L*Dd + n0)*Dd,
        Dd, acc);
    EPI_SETUP();
    #pragma unroll
    for (int mi = 0; mi < 4; mi++){
        int gm = m0 + erow + mi*16;
        #pragma unroll
        for (int ni = 0; ni < 4; ni++){
            int gn = n0 + ecol + ni*8;
            float b0v = out_b[(size_t)L*Dd + gn], b1v = out_b[(size_t)L*Dd + gn + 1];
            g_x[(size_t)gm*Dd + gn]       += acc[mi][ni][0] + b0v;
            g_x[(size_t)gm*Dd + gn + 1]   += acc[mi][ni][1] + b1v;
            g_x[(size_t)(gm+8)*Dd + gn]   += acc[mi][ni][2] + b0v;
            g_x[(size_t)(gm+8)*Dd + gn+1] += acc[mi][ni][3] + b1v;
        }
    }
}

__device__ __forceinline__ float gelu_exact(float v){
    return 0.5f * v * (1.f + erff(v * 0.70710678118654752f));
}
__device__ __forceinline__ void store_split(__nv_bfloat16* hi, __nv_bfloat16* lo, size_t o, float a, float b){
    __nv_bfloat16 h0 = __float2bfloat16(a), h1 = __float2bfloat16(b);
    __nv_bfloat162 hp; hp.x = h0; hp.y = h1;
    __nv_bfloat162 lp;
    lp.x = __float2bfloat16(a - __bfloat162float(h0));
    lp.y = __float2bfloat16(b - __bfloat162float(h1));
    *(__nv_bfloat162*)&hi[o] = hp;
    *(__nv_bfloat162*)&lo[o] = lp;
}

__global__ __launch_bounds__(256,1)
void mm_moe1(int L, const float* __restrict__ b1){
    int e = blockIdx.z;
    int count = g_cnt[e];
    int m0 = blockIdx.y*128;
    if (m0 >= count) return;
    int n0 = blockIdx.x*128;
    extern __shared__ char sm[];
    float acc[4][4][4] = {};
    mma_mainloop(sm,
        g_a1_hi + ((size_t)e*CAP + m0)*Dd, g_a1_lo + ((size_t)e*CAP + m0)*Dd,
        g_w1_hi + ((size_t)(L*Ee + e)*Ff + n0)*Dd, g_w1_lo + ((size_t)(L*Ee + e)*Ff + n0)*Dd,
        Dd, acc);
    EPI_SETUP();
    const float* be = b1 + ((size_t)(L*Ee + e))*Ff;
    #pragma unroll
    for (int mi = 0; mi < 4; mi++){
        int gr = m0 + erow + mi*16;
        #pragma unroll
        for (int ni = 0; ni < 4; ni++){
            int gn = n0 + ecol + ni*8;
            float b0v = be[gn], b1v = be[gn+1];
            if (gr < count){
                size_t o = ((size_t)e*CAP + gr)*Ff + gn;
                store_split(g_h_hi, g_h_lo, o,
                            gelu_exact(acc[mi][ni][0] + b0v),
                            gelu_exact(acc[mi][ni][1] + b1v));
            }
            if (gr + 8 < count){
                size_t o = ((size_t)e*CAP + gr + 8)*Ff + gn;
                store_split(g_h_hi, g_h_lo, o,
                            gelu_exact(acc[mi][ni][2] + b0v),
                            gelu_exact(acc[mi][ni][3] + b1v));
            }
        }
    }
}

__global__ __launch_bounds__(256,1)
void mm_moe2(int L, const float* __restrict__ b2){
    int e = blockIdx.z;
    int count = g_cnt[e];
    int m0 = blockIdx.y*128;
    if (m0 >= count) return;
    int n0 = blockIdx.x*128;
    extern __shared__ char sm[];
    float acc[4][4][4] = {};
    mma_mainloop(sm,
        g_h_hi + ((size_t)e*CAP + m0)*Ff, g_h_lo + ((size_t)e*CAP + m0)*Ff,
        g_w2_hi + ((size_t)(L*Ee + e)*Dd + n0)*Ff, g_w2_lo + ((size_t)(L*Ee + e)*Dd + n0)*Ff,
        Ff, acc);
    EPI_SETUP();
    const float* be = b2 + ((size_t)(L*Ee + e))*Dd;
    #pragma unroll
    for (int mi = 0; mi < 4; mi++){
        int gr = m0 + erow + mi*16;
        bool ok0 = gr < count, ok1 = (gr + 8) < count;
        int   t0 = ok0 ? g_tok[e*CAP + gr]     : 0;
        float w0 = ok0 ? g_wgt[e*CAP + gr]     : 0.f;
        int   t1 = ok1 ? g_tok[e*CAP + gr + 8] : 0;
        float w1 = ok1 ? g_wgt[e*CAP + gr + 8] : 0.f;
        #pragma unroll
        for (int ni = 0; ni < 4; ni++){
            int gn = n0 + ecol + ni*8;
            float b0v = be[gn], b1v = be[gn+1];
            if (ok0){
                atomicAdd(&g_x[(size_t)t0*Dd + gn],     w0*(acc[mi][ni][0] + b0v));
                atomicAdd(&g_x[(size_t)t0*Dd + gn + 1], w0*(acc[mi][ni][1] + b1v));
            }
            if (ok1){
                atomicAdd(&g_x[(size_t)t1*Dd + gn],     w1*(acc[mi][ni][2] + b0v));
                atomicAdd(&g_x[(size_t)t1*Dd + gn + 1], w1*(acc[mi][ni][3] + b1v));
            }
        }
    }
}

// ---------------- weight transpose + bf16 split: W[K][N] -> Wt[N][K] hi/lo ----------------
__global__ void split_transpose_kernel(const float* __restrict__ W,
                                       __nv_bfloat16* __restrict__ Whi,
                                       __nv_bfloat16* __restrict__ Wlo,
                                       int K, int N){
    __shared__ float tile[32][33];
    int b = blockIdx.z;
    const float* Wb = W + (size_t)b*K*N;
    int k0 = blockIdx.y*32, n0 = blockIdx.x*32;
    int tx = threadIdx.x, ty = threadIdx.y;
    #pragma unroll
    for (int i = 0; i < 32; i += 8)
        tile[ty + i][tx] = Wb[(size_t)(k0 + ty + i)*N + n0 + tx];
    __syncthreads();
    #pragma unroll
    for (int i = 0; i < 32; i += 8){
        float v = tile[tx][ty + i];
        __nv_bfloat16 h = __float2bfloat16(v);
        float lo = v - __bfloat162float(h);
        size_t o = (size_t)b*N*K + (size_t)(n0 + ty + i)*K + k0 + tx;
        Whi[o] = h; Wlo[o] = __float2bfloat16(lo);
    }
}

// ---------------- LayerNorm: MODE 1 -> affine + bf16 split (ln1), MODE 0 -> fp32 xhat (ln2) ----------------
template<int MODE>
__global__ void ln_kernel(const float* __restrict__ x,
                          const float* __restrict__ s, const float* __restrict__ b){
    int t = blockIdx.x;
    int tid = threadIdx.x;
    const float* xr = x + (size_t)t*Dd;
    float v0 = xr[tid], v1 = xr[tid+256];
    float sum = v0+v1, sq = v0*v0+v1*v1;
    #pragma unroll
    for (int o=16;o>0;o>>=1){
        sum += __shfl_xor_sync(0xffffffffu,sum,o);
        sq  += __shfl_xor_sync(0xffffffffu,sq ,o);
    }
    __shared__ float ssum[8], ssq[8];
    int w = tid>>5, l = tid&31;
    if (l==0){ ssum[w]=sum; ssq[w]=sq; }
    __syncthreads();
    float ts=0.f, tq=0.f;
    #pragma unroll
    for (int i=0;i<8;i++){ ts+=ssum[i]; tq+=ssq[i]; }
    float mu = ts*(1.f/Dd);
    float var = tq*(1.f/Dd) - mu*mu;
    float rs = rsqrtf(var + 1e-5f);
    if (MODE == 1){
        float a0 = (v0-mu)*rs*s[tid]     + b[tid];
        float a1 = (v1-mu)*rs*s[tid+256] + b[tid+256];
        __nv_bfloat16 h0 = __float2bfloat16(a0);
        __nv_bfloat16 h1 = __float2bfloat16(a1);
        size_t base = (size_t)t*Dd;
        g_xn_hi[base+tid]     = h0; g_xn_lo[base+tid]     = __float2bfloat16(a0 - __bfloat162float(h0));
        g_xn_hi[base+tid+256] = h1; g_xn_lo[base+tid+256] = __float2bfloat16(a1 - __bfloat162float(h1));
    } else {
        size_t base = (size_t)t*Dd;
        g_xn[base+tid]     = (v0-mu)*rs;
        g_xn[base+tid+256] = (v1-mu)*rs;
    }
}

// ---------------- flash attention (fp32 SIMT) -> split bf16 output ----------------
__global__ __launch_bounds__(64)
void attn_kernel(const float* __restrict__ qkv){
    int bh = blockIdx.x;
    int b = bh/Hh, h = bh%Hh;
    int q0 = blockIdx.y*64;
    int t = threadIdx.x;
    const float* base = qkv + (size_t)b*Nn*QKVC;
    float q[64];
    {
        const float* qp = base + (size_t)(q0+t)*QKVC + h*64;
        #pragma unroll
        for (int d=0; d<64; d+=4){
            float4 v = *(const float4*)&qp[d];
            q[d]=v.x*0.125f; q[d+1]=v.y*0.125f; q[d+2]=v.z*0.125f; q[d+3]=v.w*0.125f;
        }
    }
    float m = -INFINITY, lsum = 0.f;
    float acc[64];
    #pragma unroll
    for (int d=0;d<64;d++) acc[d]=0.f;
    __shared__ float ks[32][64];
    __shared__ float vs[32][64];
    for (int j0=0;j0<Nn;j0+=32){
        __syncthreads();
        for (int idx = t; idx < 32*16; idx += 64) {
            int row = idx>>4, c4 = (idx&15)*4;
            const float* kvb = base + (size_t)(j0+row)*QKVC + h*64;
            *(float4*)&ks[row][c4] = *(const float4*)&kvb[512  + c4];
            *(float4*)&vs[row][c4] = *(const float4*)&kvb[1024 + c4];
        }
        __syncthreads();
        float s[32];
        float tmax = -INFINITY;
        #pragma unroll 4
        for (int j=0;j<32;j++){
            float a0=0.f;
            #pragma unroll
            for (int d4=0; d4<64; d4+=4){
                float4 kv = *(const float4*)&ks[j][d4];
                a0 += q[d4]*kv.x + q[d4+1]*kv.y + q[d4+2]*kv.z + q[d4+3]*kv.w;
            }
            s[j]=a0; tmax = fmaxf(tmax, a0);
        }
        float mnew = fmaxf(m, tmax);
        float alpha = __expf(m - mnew);
        m = mnew;
        lsum *= alpha;
        #pragma unroll
        for (int d=0;d<64;d++) acc[d]*=alpha;
        #pragma unroll 2
        for (int j=0;j<32;j++){
            float p = __expf(s[j]-m);
            lsum += p;
            #pragma unroll
            for (int d4=0; d4<64; d4+=4){
                float4 vv = *(const float4*)&vs[j][d4];
                acc[d4]+=p*vv.x; acc[d4+1]+=p*vv.y; acc[d4+2]+=p*vv.z; acc[d4+3]+=p*vv.w;
            }
        }
    }
    float inv = 1.f/lsum;
    size_t obase = (size_t)(b*Nn + q0 + t)*Dd + h*64;
    #pragma unroll
    for (int d=0; d<64; d+=2){
        float v0 = acc[d]*inv, v1 = acc[d+1]*inv;
        __nv_bfloat16 h0 = __float2bfloat16(v0);
        __nv_bfloat16 h1 = __float2bfloat16(v1);
        __nv_bfloat162 hp; hp.x = h0; hp.y = h1;
        __nv_bfloat162 lp;
        lp.x = __float2bfloat16(v0 - __bfloat162float(h0));
        lp.y = __float2bfloat16(v1 - __bfloat162float(h1));
        *(__nv_bfloat162*)&g_o_hi[obase + d] = hp;
        *(__nv_bfloat162*)&g_o_lo[obase + d] = lp;
    }
}

// ---------------- router ----------------
__global__ void reset_cnt_kernel(){ if (threadIdx.x < Ee) g_cnt[threadIdx.x]=0; }

__global__ void router_kernel(int layer, const float* __restrict__ rtw,
                              const float* __restrict__ rtb, float* __restrict__ wout) {
    int gw = (blockIdx.x*blockDim.x + threadIdx.x) >> 5;
    int lane = threadIdx.x & 31;
    if (gw >= T) return;
    const float* xr = g_x + (size_t)gw*Dd;
    const float* w = rtw + (size_t)layer*Dd*Ee;
    float acc[8] = {};
    for (int d=lane; d<Dd; d+=32){
        float xv = xr[d];
        const float* wr = w + d*Ee;
        #pragma unroll
        for (int e=0;e<8;e++) acc[e] += xv*wr[e];
    }
    #pragma unroll
    for (int e=0;e<8;e++){
        #pragma unroll
        for (int o=16;o>0;o>>=1) acc[e] += __shfl_xor_sync(0xffffffffu, acc[e], o);
    }
    if (lane==0){
        const float* bb = rtb + layer*Ee;
        float lg[8];
        #pragma unroll
        for (int e=0;e<8;e++) lg[e] = acc[e] + bb[e];
        float m1=-INFINITY, m2=-INFINITY;
        #pragma unroll
        for (int e=0;e<8;e++){
            float v=lg[e];
            if (v>m1){ m2=m1; m1=v; } else if (v>m2){ m2=v; }
        }
        float ssum=0.f, wv[8];
        #pragma unroll
        for (int e=0;e<8;e++){
            if (lg[e] >= m2){ wv[e]=expf(lg[e]-m1); ssum+=wv[e]; } else wv[e]=0.f;
        }
        float inv = 1.f/ssum;
        float* wo = wout + ((size_t)layer*T + gw)*Ee;
        #pragma unroll
        for (int e=0;e<8;e++){
            float we = wv[e]*inv;
            wo[e] = we;
            if (wv[e] > 0.f){
                int p = atomicAdd(&g_cnt[e], 1);
                g_tok[e*CAP+p] = gw;
                g_wgt[e*CAP+p] = we;
            }
        }
    }
}

// ---------------- a1 prep: gather + per-expert LN2 affine + bf16 split ----------------
__global__ void a1_prep_kernel(int L, const float* __restrict__ ln2s, const float* __restrict__ ln2b){
    int e = blockIdx.y;
    int slot = blockIdx.x;
    if (slot >= g_cnt[e]) return;
    int tok = g_tok[e*CAP + slot];
    int tid = threadIdx.x;
    const float* se = ln2s + ((size_t)(L*Ee + e))*Dd;
    const float* be = ln2b + ((size_t)(L*Ee + e))*Dd;
    const float* xr = g_xn + (size_t)tok*Dd;
    size_t orow = ((size_t)e*CAP + slot)*Dd;
    for (int d = tid; d < Dd; d += 128){
        float v = xr[d]*se[d] + be[d];
        __nv_bfloat16 h = __float2bfloat16(v);
        g_a1_hi[orow + d] = h;
        g_a1_lo[orow + d] = __float2bfloat16(v - __bfloat162float(h));
    }
}

// ---------------- host launcher ----------------
extern "C" void kernel_launch(void* const* d_in, const int* in_sizes, int n_in,
                              void* d_out, int out_size) {
    const float* x_in  = (const float*)d_in[0];
    const float* ln1_s = (const float*)d_in[1];
    const float* ln1_b = (const float*)d_in[2];
    const float* qkv_w = (const float*)d_in[3];
    const float* out_w = (const float*)d_in[4];
    const float* out_b = (const float*)d_in[5];
    const float* rt_w  = (const float*)d_in[6];
    const float* rt_b  = (const float*)d_in[7];
    const float* ln2_s = (const float*)d_in[8];
    const float* ln2_b = (const float*)d_in[9];
    const float* w1    = (const float*)d_in[10];
    const float* b1    = (const float*)d_in[11];
    const float* w2    = (const float*)d_in[12];
    const float* b2    = (const float*)d_in[13];
    float* out = (float*)d_out;

    float *p_x, *p_qkv;
    __nv_bfloat16 *p_wq_hi, *p_wq_lo, *p_wo_hi, *p_wo_lo, *p_w1_hi, *p_w1_lo, *p_w2_hi, *p_w2_lo;
    cudaGetSymbolAddress((void**)&p_x,     g_x);
    cudaGetSymbolAddress((void**)&p_qkv,   g_qkv);
    cudaGetSymbolAddress((void**)&p_wq_hi, g_wq_hi);
    cudaGetSymbolAddress((void**)&p_wq_lo, g_wq_lo);
    cudaGetSymbolAddress((void**)&p_wo_hi, g_wo_hi);
    cudaGetSymbolAddress((void**)&p_wo_lo, g_wo_lo);
    cudaGetSymbolAddress((void**)&p_w1_hi, g_w1_hi);
    cudaGetSymbolAddress((void**)&p_w1_lo, g_w1_lo);
    cudaGetSymbolAddress((void**)&p_w2_hi, g_w2_hi);
    cudaGetSymbolAddress((void**)&p_w2_lo, g_w2_lo);

    cudaFuncSetAttribute(mm_qkv,     cudaFuncAttributeMaxDynamicSharedMemorySize, DSMEM_BYTES);
    cudaFuncSetAttribute(mm_outproj, cudaFuncAttributeMaxDynamicSharedMemorySize, DSMEM_BYTES);
    cudaFuncSetAttribute(mm_moe1,    cudaFuncAttributeMaxDynamicSharedMemorySize, DSMEM_BYTES);
    cudaFuncSetAttribute(mm_moe2,    cudaFuncAttributeMaxDynamicSharedMemorySize, DSMEM_BYTES);

    cudaMemcpyAsync(p_x, x_in, sizeof(float)*T*Dd, cudaMemcpyDeviceToDevice);

    // weight transpose + split (all layers, every launch)
    split_transpose_kernel<<<dim3(QKVC/32, Dd/32, DEPTH),    dim3(32,8)>>>(qkv_w, p_wq_hi, p_wq_lo, Dd, QKVC);
    split_transpose_kernel<<<dim3(Dd/32,   Dd/32, DEPTH),    dim3(32,8)>>>(out_w, p_wo_hi, p_wo_lo, Dd, Dd);
    split_transpose_kernel<<<dim3(Ff/32,   Dd/32, DEPTH*Ee), dim3(32,8)>>>(w1,    p_w1_hi, p_w1_lo, Dd, Ff);
    split_transpose_kernel<<<dim3(Dd/32,   Ff/32, DEPTH*Ee), dim3(32,8)>>>(w2,    p_w2_hi, p_w2_lo, Ff, Dd);

    for (int L = 0; L < DEPTH; L++){
        ln_kernel<1><<<T,256>>>(p_x, ln1_s + (size_t)L*Dd, ln1_b + (size_t)L*Dd);
        mm_qkv<<<dim3(QKVC/128, T/128), 256, DSMEM_BYTES>>>(L);
        attn_kernel<<<dim3(Bb*Hh, Nn/64), 64>>>(p_qkv);
        mm_outproj<<<dim3(Dd/128, T/128), 256, DSMEM_BYTES>>>(L, out_b);
        reset_cnt_kernel<<<1,32>>>();
        router_kernel<<<T/8, 256>>>(L, rt_w, rt_b, out + (size_t)T*Dd);
        ln_kernel<0><<<T,256>>>(p_x, nullptr, nullptr);
        a1_prep_kernel<<<dim3(CAP, Ee), 128>>>(L, ln2_s, ln2_b);
        mm_moe1<<<dim3(Ff/128, CAP/128, Ee), 256, DSMEM_BYTES>>>(L, b1);
        mm_moe2<<<dim3(Dd/128, CAP/128, Ee), 256, DSMEM_BYTES>>>(L, b2);
    }
    cudaMemcpyAsync(out, p_x, sizeof(float)*T*Dd, cudaMemcpyDeviceToDevice);
}

// round 13
// speedup vs baseline: 2.5035x; 1.3823x over previous
#include <cuda_runtime.h>
#include <cuda_bf16.h>
#include <math.h>
#include <stdint.h>

#define Bb 8
#define Nn 1024
#define Dd 512
#define Hh 8
#define Ff 2048
#define Ee 8
#define DEPTH 2
#define T (Bb*Nn)          // 8192 tokens
#define CAP T
#define QKVC (3*Dd)        // 1536

// ---------------- scratch (static device globals; no allocation) ----------------
__device__ float g_x[T*Dd];
__device__ float g_xn[T*Dd];                    // ln2 raw xhat (fp32)
__device__ float g_qkv[T*QKVC];
__device__ __nv_bfloat16 g_xn_hi[T*Dd], g_xn_lo[T*Dd];      // ln1 output split
__device__ __nv_bfloat16 g_o_hi[T*Dd],  g_o_lo[T*Dd];       // attention output split
__device__ __nv_bfloat16 g_a1_hi[(size_t)Ee*CAP*Dd], g_a1_lo[(size_t)Ee*CAP*Dd];
__device__ __nv_bfloat16 g_h_hi[(size_t)Ee*CAP*Ff],  g_h_lo[(size_t)Ee*CAP*Ff];
// weights transposed to [N][K] K-major, bf16 hi/lo
__device__ __nv_bfloat16 g_wq_hi[(size_t)DEPTH*QKVC*Dd], g_wq_lo[(size_t)DEPTH*QKVC*Dd];
__device__ __nv_bfloat16 g_wo_hi[(size_t)DEPTH*Dd*Dd],   g_wo_lo[(size_t)DEPTH*Dd*Dd];
__device__ __nv_bfloat16 g_w1_hi[(size_t)DEPTH*Ee*Ff*Dd], g_w1_lo[(size_t)DEPTH*Ee*Ff*Dd];
__device__ __nv_bfloat16 g_w2_hi[(size_t)DEPTH*Ee*Dd*Ff], g_w2_lo[(size_t)DEPTH*Ee*Dd*Ff];
__device__ int   g_cnt[Ee];
__device__ int   g_tok[Ee*CAP];
__device__ float g_wgt[Ee*CAP];

// ---------------- helpers (compute_103-safe: sm_80-era ISA only) ----------------
__device__ __forceinline__ uint32_t smem_u32(const void* p){
    uint32_t a;
    asm("{ .reg .u64 t; cvta.to.shared.u64 t, %1; cvt.u32.u64 %0, t; }" : "=r"(a) : "l"(p));
    return a;
}
#define LDM4(r, addr) \
    asm volatile("ldmatrix.sync.aligned.m8n8.x4.shared.b16 {%0,%1,%2,%3}, [%4];" \
        : "=r"((r)[0]), "=r"((r)[1]), "=r"((r)[2]), "=r"((r)[3]) : "r"(addr))
#define LDM2(r, addr) \
    asm volatile("ldmatrix.sync.aligned.m8n8.x2.shared.b16 {%0,%1}, [%2];" \
        : "=r"((r)[0]), "=r"((r)[1]) : "r"(addr))
#define MMA(acc, a, b) \
    asm volatile("mma.sync.aligned.m16n8k16.row.col.f32.bf16.bf16.f32 " \
        "{%0,%1,%2,%3},{%4,%5,%6,%7},{%8,%9},{%0,%1,%2,%3};" \
        : "+f"((acc)[0]), "+f"((acc)[1]), "+f"((acc)[2]), "+f"((acc)[3]) \
        : "r"((a)[0]), "r"((a)[1]), "r"((a)[2]), "r"((a)[3]), "r"((b)[0]), "r"((b)[1]))

#define PITCHB 80            // smem row pitch in bytes (32 bf16 + 8 pad) — ldmatrix conflict-free
#define TSB    (128*PITCHB)  // one tensor, one stage: 10240 B
#define STAGEB (4*TSB)       // Ah,Al,Bh,Bl: 40960 B
#define DSMEM_BYTES (2*STAGEB)

__device__ __forceinline__ float gelu_exact(float v){
    return 0.5f * v * (1.f + erff(v * 0.70710678118654752f));
}
__device__ __forceinline__ void store_split(__nv_bfloat16* hi, __nv_bfloat16* lo, size_t o, float a, float b){
    __nv_bfloat16 h0 = __float2bfloat16(a), h1 = __float2bfloat16(b);
    __nv_bfloat162 hp; hp.x = h0; hp.y = h1;
    __nv_bfloat162 lp;
    lp.x = __float2bfloat16(a - __bfloat162float(h0));
    lp.y = __float2bfloat16(b - __bfloat162float(h1));
    *(__nv_bfloat162*)&hi[o] = hp;
    *(__nv_bfloat162*)&lo[o] = lp;
}
// pack (a,b) into bf16x2 hi word; lo word = residuals
__device__ __forceinline__ uint32_t pack_split(float a, float b, uint32_t& lo){
    __nv_bfloat16 ha = __float2bfloat16(a), hb = __float2bfloat16(b);
    __nv_bfloat162 hp; hp.x = ha; hp.y = hb;
    __nv_bfloat162 lp;
    lp.x = __float2bfloat16(a - __bfloat162float(ha));
    lp.y = __float2bfloat16(b - __bfloat162float(hb));
    lo = *(uint32_t*)&lp;
    return *(uint32_t*)&hp;
}

// ---------------- HMMA mainloop: acc += split(A[128xK]) @ split(B[128xK])^T ----------------
__device__ __forceinline__ void mma_mainloop(
    char* sm,
    const __nv_bfloat16* __restrict__ Ah, const __nv_bfloat16* __restrict__ Al,
    const __nv_bfloat16* __restrict__ Bh, const __nv_bfloat16* __restrict__ Bl,
    int K, float acc[4][4][4])
{
    const int tid  = threadIdx.x;
    const int lane = tid & 31;
    const int wid  = tid >> 5;
    const int wm   = wid >> 2;
    const int wn   = wid & 3;
    const int NC   = K >> 5;
    const int lrow = tid >> 2;
    const int lcol = (tid & 3) * 8;
    const int scol = (tid & 3) * 16;

    const __nv_bfloat16* srcs[4] = {Ah, Al, Bh, Bl};

    const int arow = (lane & 7) + ((lane >> 3) & 1) * 8;
    const int acol = (lane >> 4) * 8;
    const int brow = lane & 7;
    const int bcol = ((lane >> 3) & 1) * 8;

    #pragma unroll
    for (int t = 0; t < 4; t++){
        uint4 a = *(const uint4*)(srcs[t] + (size_t)lrow*K + lcol);
        uint4 b = *(const uint4*)(srcs[t] + (size_t)(lrow+64)*K + lcol);
        char* d = sm + t*TSB;
        *(uint4*)(d + lrow*PITCHB + scol) = a;
        *(uint4*)(d + (lrow+64)*PITCHB + scol) = b;
    }
    __syncthreads();

    for (int kc = 0; kc < NC; kc++){
        int s = kc & 1;
        bool nxt = (kc + 1 < NC);
        uint4 v[4][2];
        if (nxt){
            int kb = (kc + 1) * 32;
            #pragma unroll
            for (int t = 0; t < 4; t++){
                v[t][0] = *(const uint4*)(srcs[t] + (size_t)lrow*K + kb + lcol);
                v[t][1] = *(const uint4*)(srcs[t] + (size_t)(lrow+64)*K + kb + lcol);
            }
        }
        uint32_t uS = smem_u32(sm + s*STAGEB);
        #pragma unroll
        for (int ks = 0; ks < 2; ks++){
            const int kk = ks * 16;
            uint32_t ah[4][4], al[4][4], bh[4][2], bl[4][2];
            #pragma unroll
            for (int mi = 0; mi < 4; mi++){
                uint32_t ro = (uint32_t)(wm*64 + mi*16 + arow)*PITCHB + (kk + acol)*2;
                LDM4(ah[mi], uS + 0*TSB + ro);
                LDM4(al[mi], uS + 1*TSB + ro);
            }
            #pragma unroll
            for (int ni = 0; ni < 4; ni++){
                uint32_t ro = (uint32_t)(wn*32 + ni*8 + brow)*PITCHB + (kk + bcol)*2;
                LDM2(bh[ni], uS + 2*TSB + ro);
                LDM2(bl[ni], uS + 3*TSB + ro);
            }
            #pragma unroll
            for (int mi = 0; mi < 4; mi++)
                #pragma unroll
                for (int ni = 0; ni < 4; ni++){
                    MMA(acc[mi][ni], ah[mi], bh[ni]);
                    MMA(acc[mi][ni], ah[mi], bl[ni]);
                    MMA(acc[mi][ni], al[mi], bh[ni]);
                }
        }
        if (nxt){
            char* d = sm + (s^1)*STAGEB;
            #pragma unroll
            for (int t = 0; t < 4; t++){
                *(uint4*)(d + t*TSB + lrow*PITCHB + scol) = v[t][0];
                *(uint4*)(d + t*TSB + (lrow+64)*PITCHB + scol) = v[t][1];
            }
            __syncthreads();
        }
    }
}

#define EPI_SETUP() \
    const int lane = threadIdx.x & 31; \
    const int wid  = threadIdx.x >> 5; \
    const int erow = (wid >> 2)*64 + (lane >> 2); \
    const int ecol = (wid & 3)*32 + (lane & 3)*2;

// ---------------- GEMM kernels ----------------
__global__ __launch_bounds__(256,1)
void mm_qkv(int L){
    int n0 = blockIdx.x*128, m0 = blockIdx.y*128;
    extern __shared__ char sm[];
    float acc[4][4][4] = {};
    mma_mainloop(sm,
        g_xn_hi + (size_t)m0*Dd, g_xn_lo + (size_t)m0*Dd,
        g_wq_hi + ((size_t)L*QKVC + n0)*Dd, g_wq_lo + ((size_t)L*QKVC + n0)*Dd,
        Dd, acc);
    EPI_SETUP();
    #pragma unroll
    for (int mi = 0; mi < 4; mi++){
        int gm = m0 + erow + mi*16;
        #pragma unroll
        for (int ni = 0; ni < 4; ni++){
            int gn = n0 + ecol + ni*8;
            *(float2*)&g_qkv[(size_t)gm*QKVC + gn]     = make_float2(acc[mi][ni][0], acc[mi][ni][1]);
            *(float2*)&g_qkv[(size_t)(gm+8)*QKVC + gn] = make_float2(acc[mi][ni][2], acc[mi][ni][3]);
        }
    }
}

__global__ __launch_bounds__(256,1)
void mm_outproj(int L, const float* __restrict__ out_b){
    int n0 = blockIdx.x*128, m0 = blockIdx.y*128;
    extern __shared__ char sm[];
    float acc[4][4][4] = {};
    mma_mainloop(sm,
        g_o_hi + (size_t)m0*Dd, g_o_lo + (size_t)m0*Dd,
        g_wo_hi + ((size_t)L*Dd + n0)*Dd, g_wo_lo + ((size_t)L*Dd + n0)*Dd,
        Dd, acc);
    EPI_SETUP();
    #pragma unroll
    for (int mi = 0; mi < 4; mi++){
        int gm = m0 + erow + mi*16;
        #pragma unroll
        for (int ni = 0; ni < 4; ni++){
            int gn = n0 + ecol + ni*8;
            float b0v = out_b[(size_t)L*Dd + gn], b1v = out_b[(size_t)L*Dd + gn + 1];
            g_x[(size_t)gm*Dd + gn]       += acc[mi][ni][0] + b0v;
            g_x[(size_t)gm*Dd + gn + 1]   += acc[mi][ni][1] + b1v;
            g_x[(size_t)(gm+8)*Dd + gn]   += acc[mi][ni][2] + b0v;
            g_x[(size_t)(gm+8)*Dd + gn+1] += acc[mi][ni][3] + b1v;
        }
    }
}

__global__ __launch_bounds__(256,1)
void mm_moe1(int L, const float* __restrict__ b1){
    int e = blockIdx.z;
    int count = g_cnt[e];
    int m0 = blockIdx.y*128;
    if (m0 >= count) return;
    int n0 = blockIdx.x*128;
    extern __shared__ char sm[];
    float acc[4][4][4] = {};
    mma_mainloop(sm,
        g_a1_hi + ((size_t)e*CAP + m0)*Dd, g_a1_lo + ((size_t)e*CAP + m0)*Dd,
        g_w1_hi + ((size_t)(L*Ee + e)*Ff + n0)*Dd, g_w1_lo + ((size_t)(L*Ee + e)*Ff + n0)*Dd,
        Dd, acc);
    EPI_SETUP();
    const float* be = b1 + ((size_t)(L*Ee + e))*Ff;
    #pragma unroll
    for (int mi = 0; mi < 4; mi++){
        int gr = m0 + erow + mi*16;
        #pragma unroll
        for (int ni = 0; ni < 4; ni++){
            int gn = n0 + ecol + ni*8;
            float b0v = be[gn], b1v = be[gn+1];
            if (gr < count){
                size_t o = ((size_t)e*CAP + gr)*Ff + gn;
                store_split(g_h_hi, g_h_lo, o,
                            gelu_exact(acc[mi][ni][0] + b0v),
                            gelu_exact(acc[mi][ni][1] + b1v));
            }
            if (gr + 8 < count){
                size_t o = ((size_t)e*CAP + gr + 8)*Ff + gn;
                store_split(g_h_hi, g_h_lo, o,
                            gelu_exact(acc[mi][ni][2] + b0v),
                            gelu_exact(acc[mi][ni][3] + b1v));
            }
        }
    }
}

__global__ __launch_bounds__(256,1)
void mm_moe2(int L, const float* __restrict__ b2){
    int e = blockIdx.z;
    int count = g_cnt[e];
    int m0 = blockIdx.y*128;
    if (m0 >= count) return;
    int n0 = blockIdx.x*128;
    extern __shared__ char sm[];
    float acc[4][4][4] = {};
    mma_mainloop(sm,
        g_h_hi + ((size_t)e*CAP + m0)*Ff, g_h_lo + ((size_t)e*CAP + m0)*Ff,
        g_w2_hi + ((size_t)(L*Ee + e)*Dd + n0)*Ff, g_w2_lo + ((size_t)(L*Ee + e)*Dd + n0)*Ff,
        Ff, acc);
    EPI_SETUP();
    const float* be = b2 + ((size_t)(L*Ee + e))*Dd;
    #pragma unroll
    for (int mi = 0; mi < 4; mi++){
        int gr = m0 + erow + mi*16;
        bool ok0 = gr < count, ok1 = (gr + 8) < count;
        int   t0 = ok0 ? g_tok[e*CAP + gr]     : 0;
        float w0 = ok0 ? g_wgt[e*CAP + gr]     : 0.f;
        int   t1 = ok1 ? g_tok[e*CAP + gr + 8] : 0;
        float w1 = ok1 ? g_wgt[e*CAP + gr + 8] : 0.f;
        #pragma unroll
        for (int ni = 0; ni < 4; ni++){
            int gn = n0 + ecol + ni*8;
            float b0v = be[gn], b1v = be[gn+1];
            if (ok0){
                atomicAdd(&g_x[(size_t)t0*Dd + gn],     w0*(acc[mi][ni][0] + b0v));
                atomicAdd(&g_x[(size_t)t0*Dd + gn + 1], w0*(acc[mi][ni][1] + b1v));
            }
            if (ok1){
                atomicAdd(&g_x[(size_t)t1*Dd + gn],     w1*(acc[mi][ni][2] + b0v));
                atomicAdd(&g_x[(size_t)t1*Dd + gn + 1], w1*(acc[mi][ni][3] + b1v));
            }
        }
    }
}

// ---------------- HMMA flash attention ----------------
// CTA: (b,h) x 128 queries. 8 warps x 16 rows. Key tiles of 64, online softmax.
#define APITCH 144                 // 64 bf16 (128B) + 16B pad: ldmatrix conflict-free
#define ATS    (64*APITCH)         // one tensor (Kh/Kl/Vh/Vl), one stage: 9216 B
#define ASTAGE (4*ATS)             // 36864 B
#define ADSMEM (2*ASTAGE)          // 73728 B

__global__ __launch_bounds__(256,1)
void attn_mma_kernel(const float* __restrict__ qkv){
    int bh = blockIdx.x;
    int b = bh >> 3, h = bh & 7;
    int q0 = blockIdx.y * 128;
    extern __shared__ char sm[];
    const int tid = threadIdx.x, lane = tid & 31, wid = tid >> 5;
    const int gq = lane >> 2, qd = lane & 3;
    const int arow = (lane & 7) + ((lane >> 3) & 1) * 8;
    const int acol = (lane >> 4) * 8;
    const int brow = lane & 7;
    const int bcol = ((lane >> 3) & 1) * 8;
    const float* base = qkv + (size_t)b*Nn*QKVC;

    // ---- Q: load+scale+split into smem, then fragments (4 k-steps)
    uint32_t qh[4][4], ql[4][4];
    {
        char* Qh = sm;
        char* Ql = sm + 128*APITCH;    // 18432
        #pragma unroll
        for (int i = 0; i < 8; i++){
            int idx = tid + i*256;
            int row = idx >> 4, d4 = (idx & 15)*4;
            float4 v = *(const float4*)(base + (size_t)(q0+row)*QKVC + h*64 + d4);
            uint32_t lo0, lo1;
            uint32_t hi0 = pack_split(v.x*0.125f, v.y*0.125f, lo0);
            uint32_t hi1 = pack_split(v.z*0.125f, v.w*0.125f, lo1);
            *(uint32_t*)(Qh + row*APITCH + d4*2)     = hi0;
            *(uint32_t*)(Qh + row*APITCH + d4*2 + 4) = hi1;
            *(uint32_t*)(Ql + row*APITCH + d4*2)     = lo0;
            *(uint32_t*)(Ql + row*APITCH + d4*2 + 4) = lo1;
        }
        __syncthreads();
        uint32_t uQh = smem_u32(Qh), uQl = smem_u32(Ql);
        #pragma unroll
        for (int ks = 0; ks < 4; ks++){
            uint32_t ro = (uint32_t)(wid*16 + arow)*APITCH + (ks*16 + acol)*2;
            LDM4(qh[ks], uQh + ro);
            LDM4(ql[ks], uQl + ro);
        }
        __syncthreads();
    }

    float oacc[8][4] = {};
    float m0 = -INFINITY, m1 = -INFINITY, l0 = 0.f, l1 = 0.f;

    // per-tile gmem prefetch registers: i 0..3 -> K rows, i 4..7 -> V rows
    uint4 v[8];
    #pragma unroll
    for (int i = 0; i < 8; i++){
        int idx = tid + (i & 3)*256;
        int row = idx >> 4, d4 = (idx & 15)*4;
        const float* src = base + (size_t)row*QKVC + ((i < 4) ? 512 : 1024) + h*64 + d4;
        v[i] = *(const uint4*)src;
    }
    // store tile 0 into stage 0
    {
        char* st = sm;
        #pragma unroll
        for (int i = 0; i < 8; i++){
            int idx = tid + (i & 3)*256;
            int row = idx >> 4, d4 = (idx & 15)*4;
            float4 f = *(float4*)&v[i];
            uint32_t lo0, lo1;
            uint32_t hi0 = pack_split(f.x, f.y, lo0);
            uint32_t hi1 = pack_split(f.z, f.w, lo1);
            if (i < 4){
                *(uint32_t*)(st + 0*ATS + row*APITCH + d4*2)     = hi0;
                *(uint32_t*)(st + 0*ATS + row*APITCH + d4*2 + 4) = hi1;
                *(uint32_t*)(st + 1*ATS + row*APITCH + d4*2)     = lo0;
                *(uint32_t*)(st + 1*ATS + row*APITCH + d4*2 + 4) = lo1;
            } else {
                __nv_bfloat162 hp0 = *(__nv_bfloat162*)&hi0, hp1 = *(__nv_bfloat162*)&hi1;
                __nv_bfloat162 lp0 = *(__nv_bfloat162*)&lo0, lp1 = *(__nv_bfloat162*)&lo1;
                __nv_bfloat16* Vh = (__nv_bfloat16*)(st + 2*ATS);
                __nv_bfloat16* Vl = (__nv_bfloat16*)(st + 3*ATS);
                Vh[(d4+0)*(APITCH/2) + row] = hp0.x; Vh[(d4+1)*(APITCH/2) + row] = hp0.y;
                Vh[(d4+2)*(APITCH/2) + row] = hp1.x; Vh[(d4+3)*(APITCH/2) + row] = hp1.y;
                Vl[(d4+0)*(APITCH/2) + row] = lp0.x; Vl[(d4+1)*(APITCH/2) + row] = lp0.y;
                Vl[(d4+2)*(APITCH/2) + row] = lp1.x; Vl[(d4+3)*(APITCH/2) + row] = lp1.y;
            }
        }
    }
    __syncthreads();

    for (int kt = 0; kt < 16; kt++){
        int s = kt & 1;
        bool nxt = (kt + 1 < 16);
        if (nxt){
            int j0 = (kt + 1) * 64;
            #pragma unroll
            for (int i = 0; i < 8; i++){
                int idx = tid + (i & 3)*256;
                int row = idx >> 4, d4 = (idx & 15)*4;
                const float* src = base + (size_t)(j0+row)*QKVC + ((i < 4) ? 512 : 1024) + h*64 + d4;
                v[i] = *(const uint4*)src;
            }
        }
        uint32_t uS = smem_u32(sm + s*ASTAGE);
        // S = Q @ K^T (split, 3 MMA)
        float sacc[8][4] = {};
        #pragma unroll
        for (int ks = 0; ks < 4; ks++){
            #pragma unroll
            for (int ni = 0; ni < 8; ni++){
                uint32_t ro = (uint32_t)(ni*8 + brow)*APITCH + (ks*16 + bcol)*2;
                uint32_t kh[2], kl[2];
                LDM2(kh, uS + 0*ATS + ro);
                LDM2(kl, uS + 1*ATS + ro);
                MMA(sacc[ni], qh[ks], kh);
                MMA(sacc[ni], qh[ks], kl);
                MMA(sacc[ni], ql[ks], kh);
            }
        }
        // online softmax
        float tm0 = -INFINITY, tm1 = -INFINITY;
        #pragma unroll
        for (int ni = 0; ni < 8; ni++){
            tm0 = fmaxf(tm0, fmaxf(sacc[ni][0], sacc[ni][1]));
            tm1 = fmaxf(tm1, fmaxf(sacc[ni][2], sacc[ni][3]));
        }
        tm0 = fmaxf(tm0, __shfl_xor_sync(0xffffffffu, tm0, 1));
        tm0 = fmaxf(tm0, __shfl_xor_sync(0xffffffffu, tm0, 2));
        tm1 = fmaxf(tm1, __shfl_xor_sync(0xffffffffu, tm1, 1));
        tm1 = fmaxf(tm1, __shfl_xor_sync(0xffffffffu, tm1, 2));
        float mn0 = fmaxf(m0, tm0), mn1 = fmaxf(m1, tm1);
        float a0 = __expf(m0 - mn0), a1 = __expf(m1 - mn1);
        m0 = mn0; m1 = mn1;
        l0 *= a0; l1 *= a1;
        float rs0 = 0.f, rs1 = 0.f;
        #pragma unroll
        for (int ni = 0; ni < 8; ni++){
            oacc[ni][0] *= a0; oacc[ni][1] *= a0;
            oacc[ni][2] *= a1; oacc[ni][3] *= a1;
            float p0 = __expf(sacc[ni][0] - m0), p1 = __expf(sacc[ni][1] - m0);
            float p2 = __expf(sacc[ni][2] - m1), p3 = __expf(sacc[ni][3] - m1);
            sacc[ni][0] = p0; sacc[ni][1] = p1; sacc[ni][2] = p2; sacc[ni][3] = p3;
            rs0 += p0 + p1; rs1 += p2 + p3;
        }
        rs0 += __shfl_xor_sync(0xffffffffu, rs0, 1);
        rs0 += __shfl_xor_sync(0xffffffffu, rs0, 2);
        rs1 += __shfl_xor_sync(0xffffffffu, rs1, 1);
        rs1 += __shfl_xor_sync(0xffffffffu, rs1, 2);
        l0 += rs0; l1 += rs1;
        // O += P @ V (split P, split V, 3 MMA). S-accum layout == A-operand layout.
        #pragma unroll
        for (int j = 0; j < 4; j++){
            uint32_t pah[4], pal[4];
            pah[0] = pack_split(sacc[2*j][0],   sacc[2*j][1],   pal[0]);
            pah[1] = pack_split(sacc[2*j][2],   sacc[2*j][3],   pal[1]);
            pah[2] = pack_split(sacc[2*j+1][0], sacc[2*j+1][1], pal[2]);
            pah[3] = pack_split(sacc[2*j+1][2], sacc[2*j+1][3], pal[3]);
            #pragma unroll
            for (int ni = 0; ni < 8; ni++){
                uint32_t ro = (uint32_t)(ni*8 + brow)*APITCH + (j*16 + bcol)*2;
                uint32_t vh[2], vl[2];
                LDM2(vh, uS + 2*ATS + ro);
                LDM2(vl, uS + 3*ATS + ro);
                MMA(oacc[ni], pah, vh);
                MMA(oacc[ni], pah, vl);
                MMA(oacc[ni], pal, vh);
            }
        }
        if (nxt){
            char* st = sm + (s^1)*ASTAGE;
            #pragma unroll
            for (int i = 0; i < 8; i++){
                int idx = tid + (i & 3)*256;
                int row = idx >> 4, d4 = (idx & 15)*4;
                float4 f = *(float4*)&v[i];
                uint32_t lo0, lo1;
                uint32_t hi0 = pack_split(f.x, f.y, lo0);
                uint32_t hi1 = pack_split(f.z, f.w, lo1);
                if (i < 4){
                    *(uint32_t*)(st + 0*ATS + row*APITCH + d4*2)     = hi0;
                    *(uint32_t*)(st + 0*ATS + row*APITCH + d4*2 + 4) = hi1;
                    *(uint32_t*)(st + 1*ATS + row*APITCH + d4*2)     = lo0;
                    *(uint32_t*)(st + 1*ATS + row*APITCH + d4*2 + 4) = lo1;
                } else {
                    __nv_bfloat162 hp0 = *(__nv_bfloat162*)&hi0, hp1 = *(__nv_bfloat162*)&hi1;
                    __nv_bfloat162 lp0 = *(__nv_bfloat162*)&lo0, lp1 = *(__nv_bfloat162*)&lo1;
                    __nv_bfloat16* Vh = (__nv_bfloat16*)(st + 2*ATS);
                    __nv_bfloat16* Vl = (__nv_bfloat16*)(st + 3*ATS);
                    Vh[(d4+0)*(APITCH/2) + row] = hp0.x; Vh[(d4+1)*(APITCH/2) + row] = hp0.y;
                    Vh[(d4+2)*(APITCH/2) + row] = hp1.x; Vh[(d4+3)*(APITCH/2) + row] = hp1.y;
                    Vl[(d4+0)*(APITCH/2) + row] = lp0.x; Vl[(d4+1)*(APITCH/2) + row] = lp0.y;
                    Vl[(d4+2)*(APITCH/2) + row] = lp1.x; Vl[(d4+3)*(APITCH/2) + row] = lp1.y;
                }
            }
            __syncthreads();
        }
    }
    // epilogue: o = O/l, bf16-split store
    float il0 = 1.f/l0, il1 = 1.f/l1;
    int r0 = q0 + wid*16 + gq;
    size_t t0o = (size_t)(b*Nn + r0)*Dd + h*64;
    size_t t1o = (size_t)(b*Nn + r0 + 8)*Dd + h*64;
    #pragma unroll
    for (int ni = 0; ni < 8; ni++){
        int c = ni*8 + qd*2;
        store_split(g_o_hi, g_o_lo, t0o + c, oacc[ni][0]*il0, oacc[ni][1]*il0);
        store_split(g_o_hi, g_o_lo, t1o + c, oacc[ni][2]*il1, oacc[ni][3]*il1);
    }
}

// ---------------- weight transpose + bf16 split ----------------
__global__ void split_transpose_kernel(const float* __restrict__ W,
                                       __nv_bfloat16* __restrict__ Whi,
                                       __nv_bfloat16* __restrict__ Wlo,
                                       int K, int N){
    __shared__ float tile[32][33];
    int b = blockIdx.z;
    const float* Wb = W + (size_t)b*K*N;
    int k0 = blockIdx.y*32, n0 = blockIdx.x*32;
    int tx = threadIdx.x, ty = threadIdx.y;
    #pragma unroll
    for (int i = 0; i < 32; i += 8)
        tile[ty + i][tx] = Wb[(size_t)(k0 + ty + i)*N + n0 + tx];
    __syncthreads();
    #pragma unroll
    for (int i = 0; i < 32; i += 8){
        float v = tile[tx][ty + i];
        __nv_bfloat16 h = __float2bfloat16(v);
        float lo = v - __bfloat162float(h);
        size_t o = (size_t)b*N*K + (size_t)(n0 + ty + i)*K + k0 + tx;
        Whi[o] = h; Wlo[o] = __float2bfloat16(lo);
    }
}

// ---------------- LayerNorm ----------------
template<int MODE>
__global__ void ln_kernel(const float* __restrict__ x,
                          const float* __restrict__ s, const float* __restrict__ b){
    int t = blockIdx.x;
    int tid = threadIdx.x;
    const float* xr = x + (size_t)t*Dd;
    float v0 = xr[tid], v1 = xr[tid+256];
    float sum = v0+v1, sq = v0*v0+v1*v1;
    #pragma unroll
    for (int o=16;o>0;o>>=1){
        sum += __shfl_xor_sync(0xffffffffu,sum,o);
        sq  += __shfl_xor_sync(0xffffffffu,sq ,o);
    }
    __shared__ float ssum[8], ssq[8];
    int w = tid>>5, l = tid&31;
    if (l==0){ ssum[w]=sum; ssq[w]=sq; }
    __syncthreads();
    float ts=0.f, tq=0.f;
    #pragma unroll
    for (int i=0;i<8;i++){ ts+=ssum[i]; tq+=ssq[i]; }
    float mu = ts*(1.f/Dd);
    float var = tq*(1.f/Dd) - mu*mu;
    float rs = rsqrtf(var + 1e-5f);
    if (MODE == 1){
        float a0 = (v0-mu)*rs*s[tid]     + b[tid];
        float a1 = (v1-mu)*rs*s[tid+256] + b[tid+256];
        __nv_bfloat16 h0 = __float2bfloat16(a0);
        __nv_bfloat16 h1 = __float2bfloat16(a1);
        size_t base = (size_t)t*Dd;
        g_xn_hi[base+tid]     = h0; g_xn_lo[base+tid]     = __float2bfloat16(a0 - __bfloat162float(h0));
        g_xn_hi[base+tid+256] = h1; g_xn_lo[base+tid+256] = __float2bfloat16(a1 - __bfloat162float(h1));
    } else {
        size_t base = (size_t)t*Dd;
        g_xn[base+tid]     = (v0-mu)*rs;
        g_xn[base+tid+256] = (v1-mu)*rs;
    }
}

// ---------------- router ----------------
__global__ void reset_cnt_kernel(){ if (threadIdx.x < Ee) g_cnt[threadIdx.x]=0; }

__global__ void router_kernel(int layer, const float* __restrict__ rtw,
                              const float* __restrict__ rtb, float* __restrict__ wout) {
    int gw = (blockIdx.x*blockDim.x + threadIdx.x) >> 5;
    int lane = threadIdx.x & 31;
    if (gw >= T) return;
    const float* xr = g_x + (size_t)gw*Dd;
    const float* w = rtw + (size_t)layer*Dd*Ee;
    float acc[8] = {};
    for (int d=lane; d<Dd; d+=32){
        float xv = xr[d];
        const float* wr = w + d*Ee;
        #pragma unroll
        for (int e=0;e<8;e++) acc[e] += xv*wr[e];
    }
    #pragma unroll
    for (int e=0;e<8;e++){
        #pragma unroll
        for (int o=16;o>0;o>>=1) acc[e] += __shfl_xor_sync(0xffffffffu, acc[e], o);
    }
    if (lane==0){
        const float* bb = rtb + layer*Ee;
        float lg[8];
        #pragma unroll
        for (int e=0;e<8;e++) lg[e] = acc[e] + bb[e];
        float m1=-INFINITY, m2=-INFINITY;
        #pragma unroll
        for (int e=0;e<8;e++){
            float v=lg[e];
            if (v>m1){ m2=m1; m1=v; } else if (v>m2){ m2=v; }
        }
        float ssum=0.f, wv[8];
        #pragma unroll
        for (int e=0;e<8;e++){
            if (lg[e] >= m2){ wv[e]=expf(lg[e]-m1); ssum+=wv[e]; } else wv[e]=0.f;
        }
        float inv = 1.f/ssum;
        float* wo = wout + ((size_t)layer*T + gw)*Ee;
        #pragma unroll
        for (int e=0;e<8;e++){
            float we = wv[e]*inv;
            wo[e] = we;
            if (wv[e] > 0.f){
                int p = atomicAdd(&g_cnt[e], 1);
                g_tok[e*CAP+p] = gw;
                g_wgt[e*CAP+p] = we;
            }
        }
    }
}

// ---------------- a1 prep ----------------
__global__ void a1_prep_kernel(int L, const float* __restrict__ ln2s, const float* __restrict__ ln2b){
    int e = blockIdx.y;
    int slot = blockIdx.x;
    if (slot >= g_cnt[e]) return;
    int tok = g_tok[e*CAP + slot];
    int tid = threadIdx.x;
    const float* se = ln2s + ((size_t)(L*Ee + e))*Dd;
    const float* be = ln2b + ((size_t)(L*Ee + e))*Dd;
    const float* xr = g_xn + (size_t)tok*Dd;
    size_t orow = ((size_t)e*CAP + slot)*Dd;
    for (int d = tid; d < Dd; d += 128){
        float v = xr[d]*se[d] + be[d];
        __nv_bfloat16 h = __float2bfloat16(v);
        g_a1_hi[orow + d] = h;
        g_a1_lo[orow + d] = __float2bfloat16(v - __bfloat162float(h));
    }
}

// ---------------- host launcher ----------------
extern "C" void kernel_launch(void* const* d_in, const int* in_sizes, int n_in,
                              void* d_out, int out_size) {
    const float* x_in  = (const float*)d_in[0];
    const float* ln1_s = (const float*)d_in[1];
    const float* ln1_b = (const float*)d_in[2];
    const float* qkv_w = (const float*)d_in[3];
    const float* out_w = (const float*)d_in[4];
    const float* out_b = (const float*)d_in[5];
    const float* rt_w  = (const float*)d_in[6];
    const float* rt_b  = (const float*)d_in[7];
    const float* ln2_s = (const float*)d_in[8];
    const float* ln2_b = (const float*)d_in[9];
    const float* w1    = (const float*)d_in[10];
    const float* b1    = (const float*)d_in[11];
    const float* w2    = (const float*)d_in[12];
    const float* b2    = (const float*)d_in[13];
    float* out = (float*)d_out;

    float *p_x, *p_qkv;
    __nv_bfloat16 *p_wq_hi, *p_wq_lo, *p_wo_hi, *p_wo_lo, *p_w1_hi, *p_w1_lo, *p_w2_hi, *p_w2_lo;
    cudaGetSymbolAddress((void**)&p_x,     g_x);
    cudaGetSymbolAddress((void**)&p_qkv,   g_qkv);
    cudaGetSymbolAddress((void**)&p_wq_hi, g_wq_hi);
    cudaGetSymbolAddress((void**)&p_wq_lo, g_wq_lo);
    cudaGetSymbolAddress((void**)&p_wo_hi, g_wo_hi);
    cudaGetSymbolAddress((void**)&p_wo_lo, g_wo_lo);
    cudaGetSymbolAddress((void**)&p_w1_hi, g_w1_hi);
    cudaGetSymbolAddress((void**)&p_w1_lo, g_w1_lo);
    cudaGetSymbolAddress((void**)&p_w2_hi, g_w2_hi);
    cudaGetSymbolAddress((void**)&p_w2_lo, g_w2_lo);

    cudaFuncSetAttribute(mm_qkv,     cudaFuncAttributeMaxDynamicSharedMemorySize, DSMEM_BYTES);
    cudaFuncSetAttribute(mm_outproj, cudaFuncAttributeMaxDynamicSharedMemorySize, DSMEM_BYTES);
    cudaFuncSetAttribute(mm_moe1,    cudaFuncAttributeMaxDynamicSharedMemorySize, DSMEM_BYTES);
    cudaFuncSetAttribute(mm_moe2,    cudaFuncAttributeMaxDynamicSharedMemorySize, DSMEM_BYTES);
    cudaFuncSetAttribute(attn_mma_kernel, cudaFuncAttributeMaxDynamicSharedMemorySize, ADSMEM);

    cudaMemcpyAsync(p_x, x_in, sizeof(float)*T*Dd, cudaMemcpyDeviceToDevice);

    split_transpose_kernel<<<dim3(QKVC/32, Dd/32, DEPTH),    dim3(32,8)>>>(qkv_w, p_wq_hi, p_wq_lo, Dd, QKVC);
    split_transpose_kernel<<<dim3(Dd/32,   Dd/32, DEPTH),    dim3(32,8)>>>(out_w, p_wo_hi, p_wo_lo, Dd, Dd);
    split_transpose_kernel<<<dim3(Ff/32,   Dd/32, DEPTH*Ee), dim3(32,8)>>>(w1,    p_w1_hi, p_w1_lo, Dd, Ff);
    split_transpose_kernel<<<dim3(Dd/32,   Ff/32, DEPTH*Ee), dim3(32,8)>>>(w2,    p_w2_hi, p_w2_lo, Ff, Dd);

    for (int L = 0; L < DEPTH; L++){
        ln_kernel<1><<<T,256>>>(p_x, ln1_s + (size_t)L*Dd, ln1_b + (size_t)L*Dd);
        mm_qkv<<<dim3(QKVC/128, T/128), 256, DSMEM_BYTES>>>(L);
        attn_mma_kernel<<<dim3(Bb*Hh, Nn/128), 256, ADSMEM>>>(p_qkv);
        mm_outproj<<<dim3(Dd/128, T/128), 256, DSMEM_BYTES>>>(L, out_b);
        reset_cnt_kernel<<<1,32>>>();
        router_kernel<<<T/8, 256>>>(L, rt_w, rt_b, out + (size_t)T*Dd);
        ln_kernel<0><<<T,256>>>(p_x, nullptr, nullptr);
        a1_prep_kernel<<<dim3(CAP, Ee), 128>>>(L, ln2_s, ln2_b);
        mm_moe1<<<dim3(Ff/128, CAP/128, Ee), 256, DSMEM_BYTES>>>(L, b1);
        mm_moe2<<<dim3(Dd/128, CAP/128, Ee), 256, DSMEM_BYTES>>>(L, b2);
    }
    cudaMemcpyAsync(out, p_x, sizeof(float)*T*Dd, cudaMemcpyDeviceToDevice);
}